// round 16
// baseline (speedup 1.0000x reference)
#include <cuda_runtime.h>
#include <cuda_fp16.h>
#include <cstdint>

// FP4(E2M1) weight-only linear via fp16 mma.sync.
// out[32,8192] = inp[32,8192] @ W^T + bias, W[n,k]=LUT(nib)*scales[n,k/16]*amax
// init: out = bias. GEMM: CTA = 256 rows x 512 k; warp = 64 rows x 32 tokens
// (sB fragment reads amortized over 2x rows). Scales staged as packed fp16.
// Epilogue: atomicAdd into L2-resident out. grid (32,16) = 512 CTAs = 1 wave.

#define TOKENS   32
#define NFEAT    8192
#define KFEAT    8192
#define NWIN     (KFEAT / 16)          // 512 mma k-steps
#define NMP      (NWIN / 2)            // 256 window-pairs
#define KSPLIT   16
#define MP_PER_CTA  (NMP / KSPLIT)     // 16
#define ROWS_CTA 256

// ---------- helpers ----------
__device__ __forceinline__ uint32_t dec16(uint32_t b){   // byte -> fp16x2 LUT pair (exact)
    uint32_t h = __byte_perm(0x3E3C3800u, 0x46444240u, b & 0x77u);
    uint32_t r = __byte_perm(h, 0u, 0x1404u);
    return r | ((b & 0x8u) << 12) | ((b & 0x80u) << 24);
}
__device__ __forceinline__ uint32_t hmul2(uint32_t a, uint32_t b){
    uint32_t r; asm("mul.rn.f16x2 %0, %1, %2;" : "=r"(r) : "r"(a), "r"(b)); return r;
}
__device__ __forceinline__ uint32_t pack_f16x2(float lo, float hi){
    uint32_t r; asm("cvt.rn.f16x2.f32 %0, %1, %2;" : "=r"(r) : "f"(hi), "f"(lo)); return r;
}
__device__ __forceinline__ void mma_acc(
    float& d0, float& d1, float& d2, float& d3,
    uint32_t a0, uint32_t a1, uint32_t a2, uint32_t a3,
    uint32_t b0, uint32_t b1)
{
    asm("mma.sync.aligned.m16n8k16.row.col.f32.f16.f16.f32 "
        "{%0,%1,%2,%3}, {%4,%5,%6,%7}, {%8,%9}, {%0,%1,%2,%3};"
        : "+f"(d0), "+f"(d1), "+f"(d2), "+f"(d3)
        : "r"(a0), "r"(a1), "r"(a2), "r"(a3), "r"(b0), "r"(b1));
}

// ---------------- init: out = bias ----------------
__global__ void init_kernel(const float* __restrict__ bias, float* __restrict__ out){
    int i4 = blockIdx.x * blockDim.x + threadIdx.x;
    if (i4 >= (TOKENS * NFEAT) / 4) return;
    const float4 b = *reinterpret_cast<const float4*>(bias + ((i4 * 4) & (NFEAT - 1)));
    reinterpret_cast<float4*>(out)[i4] = b;
}

// ---------------- GEMM kernel ----------------
// grid (32, 16) = 512 CTAs, 128 thr (4 warps), occ 4 (48 KB smem).
__global__ void __launch_bounds__(128, 4) fp4_gemm_kernel(
    const int*   __restrict__ qw,       // [N, K/2] one packed byte per int32
    const float* __restrict__ scales,   // [N, K/16]
    const float* __restrict__ inp,      // [M, K]
    const float* __restrict__ amax,     // [1]
    float*       __restrict__ out)      // [M, N], pre-initialized with bias
{
    __shared__ __align__(16) uint4    sB[MP_PER_CTA * 128];        // 32 KB [mp][g*32+lane]
    __shared__ __align__(4)  uint32_t sS[MP_PER_CTA * ROWS_CTA];   // 16 KB [mp][row] fp16x2

    const int tid = threadIdx.x, wid = tid >> 5, lane = tid & 31;
    const int c  = lane & 3, rl = lane >> 2;
    const int nb0 = blockIdx.x * ROWS_CTA;
    const int mpb = blockIdx.y * MP_PER_CTA;
    const float am = __ldg(amax);

    // ---- stage activation fragments (tokens x 512 k), amax folded ----
    {
        const int n = wid * 8 + rl;                  // token row 0..31
        const float* arow = inp + (size_t)n * KFEAT + 8 * c;
        #pragma unroll
        for (int i = 0; i < MP_PER_CTA; ++i){
            const int k0 = 32 * (mpb + i);
            const float4 a = *reinterpret_cast<const float4*>(arow + k0);
            const float4 b = *reinterpret_cast<const float4*>(arow + k0 + 4);
            sB[i * 128 + wid * 32 + lane] =
                make_uint4(pack_f16x2(a.x * am, a.y * am), pack_f16x2(a.z * am, a.w * am),
                           pack_f16x2(b.x * am, b.y * am), pack_f16x2(b.z * am, b.w * am));
        }
    }
    // ---- stage scales as packed fp16 pairs: thread owns rows tid, tid+128 ----
    {
        #pragma unroll
        for (int rr = 0; rr < 2; ++rr){
            const int row = rr * 128 + tid;
            const float4* sp = reinterpret_cast<const float4*>(
                scales + (size_t)(nb0 + row) * NWIN + mpb * 2);
            #pragma unroll
            for (int w4 = 0; w4 < MP_PER_CTA / 2; ++w4){
                const float4 v = __ldg(sp + w4);
                sS[(2 * w4    ) * ROWS_CTA + row] = pack_f16x2(v.x, v.y);
                sS[(2 * w4 + 1) * ROWS_CTA + row] = pack_f16x2(v.z, v.w);
            }
        }
    }
    __syncthreads();

    // ---- main loop: 64 rows/warp, only qweight touches global ----
    const int warp_row = wid * 64 + rl;              // local row base (rb*32+8j offsets added)
    const int r0 = nb0 + warp_row;
    const bool hiblk = (lane & 2) != 0;

    float acc[2][2][4][4];                           // [rb][m-block][g][frag]
    #pragma unroll
    for (int rb = 0; rb < 2; ++rb)
        #pragma unroll
        for (int bk = 0; bk < 2; ++bk)
            #pragma unroll
            for (int g = 0; g < 4; ++g)
                #pragma unroll
                for (int j = 0; j < 4; ++j) acc[rb][bk][g][j] = 0.f;

    // uint4 row stride = (KFEAT/2)/4 = 1024
    const uint4* qbase = reinterpret_cast<const uint4*>(qw + (size_t)r0 * (KFEAT / 2))
                         + c + (size_t)mpb * 4;

    #pragma unroll 2
    for (int mpl = 0; mpl < MP_PER_CTA; ++mpl){
        // activation fragments from SMEM (shared by all 4 warps)
        uint4 bf[4];
        #pragma unroll
        for (int g = 0; g < 4; ++g)
            bf[g] = sB[mpl * 128 + g * 32 + lane];

        #pragma unroll
        for (int rb = 0; rb < 2; ++rb){
            // q for this 32-row subset: rows warp_row + rb*32 + {0,8,16,24}
            const uint4* qp = qbase + (size_t)(rb * 32) * 1024 + (size_t)mpl * 4;
            const uint4 q0 = __ldg(qp            );
            const uint4 q1 = __ldg(qp +  8 * 1024);
            const uint4 q2 = __ldg(qp + 16 * 1024);
            const uint4 q3 = __ldg(qp + 24 * 1024);

            // packed fp16 scales (broadcast LDS.32 within lane quads)
            const int lr = warp_row + rb * 32;
            const uint32_t v0 = sS[mpl * ROWS_CTA + lr     ];
            const uint32_t v1 = sS[mpl * ROWS_CTA + lr +  8];
            const uint32_t v2 = sS[mpl * ROWS_CTA + lr + 16];
            const uint32_t v3 = sS[mpl * ROWS_CTA + lr + 24];
            const uint32_t sel = hiblk ? 0x3232u : 0x1010u;
            const uint32_t h0 = __byte_perm(v0, v0, sel);
            const uint32_t h1 = __byte_perm(v1, v1, sel);
            const uint32_t h2 = __byte_perm(v2, v2, sel);
            const uint32_t h3 = __byte_perm(v3, v3, sel);

            {   // e = 0 (k 0..15 of pair)
                const uint32_t a00 = hmul2(dec16(q0.x), h0), a02 = hmul2(dec16(q0.y), h0);
                const uint32_t a01 = hmul2(dec16(q1.x), h1), a03 = hmul2(dec16(q1.y), h1);
                const uint32_t a10 = hmul2(dec16(q2.x), h2), a12 = hmul2(dec16(q2.y), h2);
                const uint32_t a11 = hmul2(dec16(q3.x), h3), a13 = hmul2(dec16(q3.y), h3);
                #pragma unroll
                for (int g = 0; g < 4; ++g){
                    mma_acc(acc[rb][0][g][0], acc[rb][0][g][1], acc[rb][0][g][2], acc[rb][0][g][3],
                            a00, a01, a02, a03, bf[g].x, bf[g].y);
                    mma_acc(acc[rb][1][g][0], acc[rb][1][g][1], acc[rb][1][g][2], acc[rb][1][g][3],
                            a10, a11, a12, a13, bf[g].x, bf[g].y);
                }
            }
            {   // e = 1 (k 16..31 of pair)
                const uint32_t a00 = hmul2(dec16(q0.z), h0), a02 = hmul2(dec16(q0.w), h0);
                const uint32_t a01 = hmul2(dec16(q1.z), h1), a03 = hmul2(dec16(q1.w), h1);
                const uint32_t a10 = hmul2(dec16(q2.z), h2), a12 = hmul2(dec16(q2.w), h2);
                const uint32_t a11 = hmul2(dec16(q3.z), h3), a13 = hmul2(dec16(q3.w), h3);
                #pragma unroll
                for (int g = 0; g < 4; ++g){
                    mma_acc(acc[rb][0][g][0], acc[rb][0][g][1], acc[rb][0][g][2], acc[rb][0][g][3],
                            a00, a01, a02, a03, bf[g].z, bf[g].w);
                    mma_acc(acc[rb][1][g][0], acc[rb][1][g][1], acc[rb][1][g][2], acc[rb][1][g][3],
                            a10, a11, a12, a13, bf[g].z, bf[g].w);
                }
            }
        }
    }

    // ---- epilogue: RED.F32 into L2-resident out ----
    #pragma unroll
    for (int rb = 0; rb < 2; ++rb){
        const int rr = r0 + rb * 32;
        #pragma unroll
        for (int g = 0; g < 4; ++g){
            const int t0c = g * 8 + 2 * c;
            atomicAdd(out + (size_t)t0c       * NFEAT + rr     , acc[rb][0][g][0]);
            atomicAdd(out + (size_t)(t0c + 1) * NFEAT + rr     , acc[rb][0][g][1]);
            atomicAdd(out + (size_t)t0c       * NFEAT + rr +  8, acc[rb][0][g][2]);
            atomicAdd(out + (size_t)(t0c + 1) * NFEAT + rr +  8, acc[rb][0][g][3]);
            atomicAdd(out + (size_t)t0c       * NFEAT + rr + 16, acc[rb][1][g][0]);
            atomicAdd(out + (size_t)(t0c + 1) * NFEAT + rr + 16, acc[rb][1][g][1]);
            atomicAdd(out + (size_t)t0c       * NFEAT + rr + 24, acc[rb][1][g][2]);
            atomicAdd(out + (size_t)(t0c + 1) * NFEAT + rr + 24, acc[rb][1][g][3]);
        }
    }
}

extern "C" void kernel_launch(void* const* d_in, const int* in_sizes, int n_in,
                              void* d_out, int out_size)
{
    const float* inp    = (const float*)d_in[0];
    const int*   qw     = (const int*)  d_in[1];
    const float* scales = (const float*)d_in[2];
    const float* amax   = (const float*)d_in[3];
    const float* bias   = (const float*)d_in[4];
    float* out = (float*)d_out;

    init_kernel<<<(TOKENS * NFEAT / 4 + 255) / 256, 256>>>(bias, out);

    dim3 grid(NFEAT / ROWS_CTA, KSPLIT);
    fp4_gemm_kernel<<<grid, 128>>>(qw, scales, inp, amax, out);
}

// round 17
// speedup vs baseline: 1.0186x; 1.0186x over previous
#include <cuda_runtime.h>
#include <cuda_fp16.h>
#include <cstdint>

// FP4(E2M1) weight-only linear via fp16 mma.sync.
// out[32,8192] = inp[32,8192] @ W^T + bias, W[n,k]=LUT(nib)*scales[n,k/16]*amax
// R15 structure (best: SMEM-staged activation fragments + scales, q-only global
// loop, atomicAdd epilogue) with a batched 4-byte decoder: pack payload bytes,
// 2-bytes-per-PRMT table lookup, multiply-spread signs. Bit-identical math.

#define TOKENS   32
#define NFEAT    8192
#define KFEAT    8192
#define NWIN     (KFEAT / 16)          // 512 mma k-steps
#define NMP      (NWIN / 2)            // 256 window-pairs
#define KSPLIT   16
#define MP_PER_CTA  (NMP / KSPLIT)     // 16

// ---------- helpers ----------
__device__ __forceinline__ uint32_t hmul2(uint32_t a, uint32_t b){
    uint32_t r; asm("mul.rn.f16x2 %0, %1, %2;" : "=r"(r) : "r"(a), "r"(b)); return r;
}
__device__ __forceinline__ uint32_t dup_f16(float s){
    uint32_t r; asm("cvt.rn.f16x2.f32 %0, %1, %1;" : "=r"(r) : "f"(s)); return r;
}
__device__ __forceinline__ uint32_t pack_f16x2(float lo, float hi){
    uint32_t r; asm("cvt.rn.f16x2.f32 %0, %1, %2;" : "=r"(r) : "f"(hi), "f"(lo)); return r;
}
// Batched decode: uint4 (4 payload bytes, one per word, each < 256) + packed
// fp16x2 scale -> 4 scaled fp16x2 A-registers. A[0],A[1] = words x,y (e=0);
// A[2],A[3] = words z,w (e=1). Bit-identical to the per-word dec16 path.
__device__ __forceinline__ void dec4(const uint4 q, uint32_t hs, uint32_t A[4]){
    const uint32_t t1   = __byte_perm(q.x, q.y, 0x0040u);        // {b0, b1, -, -}
    const uint32_t t2   = __byte_perm(q.z, q.w, 0x0040u);        // {b2, b3, -, -}
    const uint32_t comb = __byte_perm(t1, t2, 0x5410u);          // {b0, b1, b2, b3}
    const uint32_t bs   = comb & 0x77777777u;                    // masked nibbles
    const uint32_t h01  = __byte_perm(0x3E3C3800u, 0x46444240u, bs);        // T[b0.lo],T[b0.hi],T[b1.lo],T[b1.hi]
    const uint32_t h23  = __byte_perm(0x3E3C3800u, 0x46444240u, bs >> 16);  // same for b2,b3
    const uint32_t m0 = __byte_perm(h01, 0u, 0x1404u);           // {0,T[b0.lo],0,T[b0.hi]}
    const uint32_t m1 = __byte_perm(h01, 0u, 0x3424u);           // {0,T[b1.lo],0,T[b1.hi]}
    const uint32_t m2 = __byte_perm(h23, 0u, 0x1404u);
    const uint32_t m3 = __byte_perm(h23, 0u, 0x3424u);
    // sign spread: bit3 -> bit15, bit7 -> bit31 (clean since word < 256)
    A[0] = hmul2(m0 | ((q.x * 0x01001000u) & 0x80008000u), hs);
    A[1] = hmul2(m1 | ((q.y * 0x01001000u) & 0x80008000u), hs);
    A[2] = hmul2(m2 | ((q.z * 0x01001000u) & 0x80008000u), hs);
    A[3] = hmul2(m3 | ((q.w * 0x01001000u) & 0x80008000u), hs);
}
__device__ __forceinline__ void mma_acc(
    float& d0, float& d1, float& d2, float& d3,
    uint32_t a0, uint32_t a1, uint32_t a2, uint32_t a3,
    uint32_t b0, uint32_t b1)
{
    asm("mma.sync.aligned.m16n8k16.row.col.f32.f16.f16.f32 "
        "{%0,%1,%2,%3}, {%4,%5,%6,%7}, {%8,%9}, {%0,%1,%2,%3};"
        : "+f"(d0), "+f"(d1), "+f"(d2), "+f"(d3)
        : "r"(a0), "r"(a1), "r"(a2), "r"(a3), "r"(b0), "r"(b1));
}

// ---------------- init: out = bias ----------------
__global__ void init_kernel(const float* __restrict__ bias, float* __restrict__ out){
    int i4 = blockIdx.x * blockDim.x + threadIdx.x;
    if (i4 >= (TOKENS * NFEAT) / 4) return;
    const float4 b = *reinterpret_cast<const float4*>(bias + ((i4 * 4) & (NFEAT - 1)));
    reinterpret_cast<float4*>(out)[i4] = b;
}

// ---------------- GEMM kernel ----------------
// grid (64, 16) = 1024 CTAs, 128 thr (4 warps), occ 4 (48 KB smem).
// Warp = 32 weight rows x 32 tokens; CTA = 128 rows x 512 k.
__global__ void __launch_bounds__(128, 4) fp4_gemm_kernel(
    const int*   __restrict__ qw,       // [N, K/2] one packed byte per int32
    const float* __restrict__ scales,   // [N, K/16]
    const float* __restrict__ inp,      // [M, K]
    const float* __restrict__ amax,     // [1]
    float*       __restrict__ out)      // [M, N], pre-initialized with bias
{
    __shared__ __align__(16) uint4  sB[MP_PER_CTA * 128];   // 32 KB [mp][g*32+lane]
    __shared__ __align__(8)  float2 sS[MP_PER_CTA * 128];   // 16 KB [mp][local row]

    const int tid = threadIdx.x, wid = tid >> 5, lane = tid & 31;
    const int c  = lane & 3, rl = lane >> 2;
    const int nb0 = blockIdx.x * 128;
    const int mpb = blockIdx.y * MP_PER_CTA;
    const float am = __ldg(amax);

    // ---- stage activation fragments: thread owns (g=wid, lane), loops mp ----
    {
        const int n  = wid * 8 + rl;                 // token row 0..31
        const float* arow = inp + (size_t)n * KFEAT + 8 * c;
        #pragma unroll
        for (int i = 0; i < MP_PER_CTA; ++i){
            const int k0 = 32 * (mpb + i);
            const float4 a = *reinterpret_cast<const float4*>(arow + k0);
            const float4 b = *reinterpret_cast<const float4*>(arow + k0 + 4);
            sB[i * 128 + wid * 32 + lane] =
                make_uint4(pack_f16x2(a.x * am, a.y * am), pack_f16x2(a.z * am, a.w * am),
                           pack_f16x2(b.x * am, b.y * am), pack_f16x2(b.z * am, b.w * am));
        }
    }
    // ---- stage scales: thread tid owns global row nb0+tid ----
    {
        const float4* sp = reinterpret_cast<const float4*>(
            scales + (size_t)(nb0 + tid) * NWIN + mpb * 2);
        #pragma unroll
        for (int m4 = 0; m4 < MP_PER_CTA / 2; ++m4){
            const float4 v = __ldg(sp + m4);
            sS[(2 * m4    ) * 128 + tid] = make_float2(v.x, v.y);
            sS[(2 * m4 + 1) * 128 + tid] = make_float2(v.z, v.w);
        }
    }
    __syncthreads();

    // ---- main loop: only qweight touches global ----
    const int r0 = nb0 + wid * 32 + rl;              // rows r0,+8,+16,+24
    const int lrow = wid * 32 + rl;
    const bool hiblk = (lane & 2) != 0;

    float acc[4][8];
    #pragma unroll
    for (int g = 0; g < 4; ++g)
        #pragma unroll
        for (int j = 0; j < 8; ++j) acc[g][j] = 0.f;

    const uint4* qr0 = reinterpret_cast<const uint4*>(qw + (size_t)(r0     ) * (KFEAT / 2)) + c + (size_t)mpb * 4;
    const uint4* qr1 = reinterpret_cast<const uint4*>(qw + (size_t)(r0 +  8) * (KFEAT / 2)) + c + (size_t)mpb * 4;
    const uint4* qr2 = reinterpret_cast<const uint4*>(qw + (size_t)(r0 + 16) * (KFEAT / 2)) + c + (size_t)mpb * 4;
    const uint4* qr3 = reinterpret_cast<const uint4*>(qw + (size_t)(r0 + 24) * (KFEAT / 2)) + c + (size_t)mpb * 4;

    // register prefetch of iteration 0's q
    uint4 qc0 = __ldg(qr0), qc1 = __ldg(qr1), qc2 = __ldg(qr2), qc3 = __ldg(qr3);

    #pragma unroll 2
    for (int mpl = 0; mpl < MP_PER_CTA; ++mpl){
        // prefetch next iteration's q (clamped at tail)
        const int nx = (mpl + 1 < MP_PER_CTA) ? (mpl + 1) : mpl;
        const uint4 qn0 = __ldg(qr0 + nx * 4);
        const uint4 qn1 = __ldg(qr1 + nx * 4);
        const uint4 qn2 = __ldg(qr2 + nx * 4);
        const uint4 qn3 = __ldg(qr3 + nx * 4);

        // scales from SMEM
        const float2 s0 = sS[mpl * 128 + lrow     ];
        const float2 s1 = sS[mpl * 128 + lrow +  8];
        const float2 s2 = sS[mpl * 128 + lrow + 16];
        const float2 s3 = sS[mpl * 128 + lrow + 24];
        const uint32_t h0 = dup_f16(hiblk ? s0.y : s0.x);
        const uint32_t h1 = dup_f16(hiblk ? s1.y : s1.x);
        const uint32_t h2 = dup_f16(hiblk ? s2.y : s2.x);
        const uint32_t h3 = dup_f16(hiblk ? s3.y : s3.x);

        // activation fragments from SMEM
        uint4 bf[4];
        #pragma unroll
        for (int g = 0; g < 4; ++g)
            bf[g] = sB[mpl * 128 + g * 32 + lane];

        // batched decode: 4 A-regs per row-group
        uint32_t A0[4], A1[4], A2[4], A3[4];
        dec4(qc0, h0, A0);
        dec4(qc1, h1, A1);
        dec4(qc2, h2, A2);
        dec4(qc3, h3, A3);

        {   // e = 0 (k 0..15 of pair)
            #pragma unroll
            for (int g = 0; g < 4; ++g){
                mma_acc(acc[g][0], acc[g][1], acc[g][2], acc[g][3],
                        A0[0], A1[0], A0[1], A1[1], bf[g].x, bf[g].y);
                mma_acc(acc[g][4], acc[g][5], acc[g][6], acc[g][7],
                        A2[0], A3[0], A2[1], A3[1], bf[g].x, bf[g].y);
            }
        }
        {   // e = 1 (k 16..31 of pair)
            #pragma unroll
            for (int g = 0; g < 4; ++g){
                mma_acc(acc[g][0], acc[g][1], acc[g][2], acc[g][3],
                        A0[2], A1[2], A0[3], A1[3], bf[g].z, bf[g].w);
                mma_acc(acc[g][4], acc[g][5], acc[g][6], acc[g][7],
                        A2[2], A3[2], A2[3], A3[3], bf[g].z, bf[g].w);
            }
        }

        qc0 = qn0; qc1 = qn1; qc2 = qn2; qc3 = qn3;
    }

    // ---- epilogue: RED.F32 into L2-resident out ----
    #pragma unroll
    for (int g = 0; g < 4; ++g){
        const int t0c = g * 8 + 2 * c;
        atomicAdd(out + (size_t)t0c       * NFEAT + r0     , acc[g][0]);
        atomicAdd(out + (size_t)(t0c + 1) * NFEAT + r0     , acc[g][1]);
        atomicAdd(out + (size_t)t0c       * NFEAT + r0 +  8, acc[g][2]);
        atomicAdd(out + (size_t)(t0c + 1) * NFEAT + r0 +  8, acc[g][3]);
        atomicAdd(out + (size_t)t0c       * NFEAT + r0 + 16, acc[g][4]);
        atomicAdd(out + (size_t)(t0c + 1) * NFEAT + r0 + 16, acc[g][5]);
        atomicAdd(out + (size_t)t0c       * NFEAT + r0 + 24, acc[g][6]);
        atomicAdd(out + (size_t)(t0c + 1) * NFEAT + r0 + 24, acc[g][7]);
    }
}

extern "C" void kernel_launch(void* const* d_in, const int* in_sizes, int n_in,
                              void* d_out, int out_size)
{
    const float* inp    = (const float*)d_in[0];
    const int*   qw     = (const int*)  d_in[1];
    const float* scales = (const float*)d_in[2];
    const float* amax   = (const float*)d_in[3];
    const float* bias   = (const float*)d_in[4];
    float* out = (float*)d_out;

    init_kernel<<<(TOKENS * NFEAT / 4 + 255) / 256, 256>>>(bias, out);

    dim3 grid(NFEAT / 128, KSPLIT);
    fp4_gemm_kernel<<<grid, 128>>>(qw, scales, inp, amax, out);
}